// round 2
// baseline (speedup 1.0000x reference)
#include <cuda_runtime.h>
#include <math.h>

// Problem constants (fixed shapes per reference setup_inputs)
#define NB 8192      // batch
#define ND 256       // embedding dim
#define TI 64        // anchors per block
#define TJ 64        // j-tile
#define NTHREADS 256
#define NBLOCKS (NB / TI)   // 128

#define BIGNEG -1e30f

// Scratch (no allocations allowed -> device globals)
__device__ float g_e[NB * ND];        // L2-normalized embeddings, 32 MB
__device__ float g_psum[NBLOCKS];     // per-block loss partial sums
__device__ int   g_pcnt[NBLOCKS];     // per-block valid-anchor counts

// ---------------------------------------------------------------------------
// Kernel 1: row L2 normalization. One block per row, one thread per element.
// ---------------------------------------------------------------------------
__global__ __launch_bounds__(ND) void normalize_kernel(const float* __restrict__ emb) {
    const int row = blockIdx.x;
    const int t = threadIdx.x;
    float v = emb[row * ND + t];
    float s = v * v;
    #pragma unroll
    for (int o = 16; o > 0; o >>= 1) s += __shfl_xor_sync(0xFFFFFFFFu, s, o);
    __shared__ float ws[ND / 32];
    if ((t & 31) == 0) ws[t >> 5] = s;
    __syncthreads();
    float tot = 0.f;
    #pragma unroll
    for (int w = 0; w < ND / 32; w++) tot += ws[w];
    float inv = 1.0f / sqrtf(tot);
    g_e[row * ND + t] = v * inv;
}

// ---------------------------------------------------------------------------
// Kernel 2: fused sims GEMM + contrastive epilogue.
//
// SMEM layout: k-major tiles As[k][i], Bs[k][j] (k=0..255, 64 cols), with a
// float4-group XOR swizzle: element (k, i) lives at
//   float index  k*64 + 4*((i>>2) ^ (k&15)) + (i&3)
// so inner-loop LDS.128 reads are conflict-free.
//
// Stabilizer: sims are bounded by M = 1/0.7 (cosine <= 1), so exp(v - M) is
// always in [e^-2.86, 1]. Constant-M logsumexp is mathematically identical to
// the reference's per-anchor-max logsumexp.
// ---------------------------------------------------------------------------
__global__ __launch_bounds__(NTHREADS) void loss_kernel(const int* __restrict__ cats) {
    extern __shared__ __align__(16) float smem[];
    float* As = smem;               // ND * TI floats = 64 KB
    float* Bs = smem + ND * TI;     // ND * TJ floats = 64 KB
    __shared__ int catI[TI];
    __shared__ int catJ[TJ];
    __shared__ float rsum[NTHREADS / 32];
    __shared__ int   rcnt[NTHREADS / 32];

    const int t  = threadIdx.x;
    const int tx = t & 15;          // 16 col-groups of 4
    const int ty = t >> 4;          // 16 row-groups of 4
    const int i0 = blockIdx.x * TI;

    const float INVT = 1.0f / 0.7f; // also the stabilizer M (max possible sim)

    // ---- Load + swizzle the A tile (all K, once per block) ----
    {
        const int row = t >> 2;     // 0..63
        const int c0  = t & 3;
        const int g = row >> 2, rr = row & 3;
        const float4* src = reinterpret_cast<const float4*>(g_e + (size_t)(i0 + row) * ND);
        #pragma unroll
        for (int m = 0; m < 16; m++) {
            const int c4 = c0 + 4 * m;        // float4 index along k: covers 0..63
            const float4 v = src[c4];
            const int k = 4 * c4;
            As[(k + 0) * 64 + (((g ^ ((k + 0) & 15)) << 2) | rr)] = v.x;
            As[(k + 1) * 64 + (((g ^ ((k + 1) & 15)) << 2) | rr)] = v.y;
            As[(k + 2) * 64 + (((g ^ ((k + 2) & 15)) << 2) | rr)] = v.z;
            As[(k + 3) * 64 + (((g ^ ((k + 3) & 15)) << 2) | rr)] = v.w;
        }
    }
    if (t < TI) catI[t] = cats[i0 + t];

    // Per-thread running stats for my 4 anchor rows
    float posm[4], ns[4];
    #pragma unroll
    for (int r = 0; r < 4; r++) { posm[r] = BIGNEG; ns[r] = 0.f; }

    for (int j0 = 0; j0 < NB; j0 += TJ) {
        __syncthreads();   // previous tile fully consumed (also covers A-tile visibility on iter 0)
        {
            const int row = t >> 2;
            const int c0  = t & 3;
            const int g = row >> 2, rr = row & 3;
            const float4* src = reinterpret_cast<const float4*>(g_e + (size_t)(j0 + row) * ND);
            #pragma unroll
            for (int m = 0; m < 16; m++) {
                const int c4 = c0 + 4 * m;
                const float4 v = src[c4];
                const int k = 4 * c4;
                Bs[(k + 0) * 64 + (((g ^ ((k + 0) & 15)) << 2) | rr)] = v.x;
                Bs[(k + 1) * 64 + (((g ^ ((k + 1) & 15)) << 2) | rr)] = v.y;
                Bs[(k + 2) * 64 + (((g ^ ((k + 2) & 15)) << 2) | rr)] = v.z;
                Bs[(k + 3) * 64 + (((g ^ ((k + 3) & 15)) << 2) | rr)] = v.w;
            }
        }
        if (t < TJ) catJ[t] = cats[j0 + t];
        __syncthreads();

        float acc[4][4];
        #pragma unroll
        for (int r = 0; r < 4; r++)
            #pragma unroll
            for (int c = 0; c < 4; c++) acc[r][c] = 0.f;

        const float4* As4 = reinterpret_cast<const float4*>(As);
        const float4* Bs4 = reinterpret_cast<const float4*>(Bs);
        #pragma unroll 8
        for (int k = 0; k < ND; k++) {
            const int sw = k & 15;
            const float4 a = As4[k * 16 + (ty ^ sw)];
            const float4 b = Bs4[k * 16 + (tx ^ sw)];
            acc[0][0] += a.x * b.x; acc[0][1] += a.x * b.y; acc[0][2] += a.x * b.z; acc[0][3] += a.x * b.w;
            acc[1][0] += a.y * b.x; acc[1][1] += a.y * b.y; acc[1][2] += a.y * b.z; acc[1][3] += a.y * b.w;
            acc[2][0] += a.z * b.x; acc[2][1] += a.z * b.y; acc[2][2] += a.z * b.z; acc[2][3] += a.z * b.w;
            acc[3][0] += a.w * b.x; acc[3][1] += a.w * b.y; acc[3][2] += a.w * b.z; acc[3][3] += a.w * b.w;
        }

        // Epilogue: masked max-pos / sum-exp-neg, predicated (no divergence)
        const int jb = j0 + 4 * tx;
        int cj[4];
        #pragma unroll
        for (int c = 0; c < 4; c++) cj[c] = catJ[4 * tx + c];

        #pragma unroll
        for (int r = 0; r < 4; r++) {
            const int i  = i0 + 4 * ty + r;
            const int ci = catI[4 * ty + r];
            #pragma unroll
            for (int c = 0; c < 4; c++) {
                const float v = acc[r][c] * INVT;
                const bool same = (ci == cj[c]);
                const float ev = __expf(v - INVT);
                ns[r]   += same ? 0.f : ev;
                posm[r] = fmaxf(posm[r], (same && (i != jb + c)) ? v : BIGNEG);
            }
        }
    }

    // ---- Combine across the 16 threads (one half-warp) sharing each anchor row ----
    float lsum = 0.f; int lcnt = 0;
    #pragma unroll
    for (int r = 0; r < 4; r++) {
        float p = posm[r];
        float s = ns[r];
        #pragma unroll
        for (int o = 1; o < 16; o <<= 1) {
            p = fmaxf(p, __shfl_xor_sync(0xFFFFFFFFu, p, o));
            s += __shfl_xor_sync(0xFFFFFFFFu, s, o);
        }
        if (tx == 0) {
            const bool valid = (p > -1e29f) && (s > 0.f);
            if (valid) {
                const float lse = INVT + logf(__expf(p - INVT) + s);
                lsum += lse - p;
                lcnt += 1;
            }
        }
    }

    // ---- Deterministic block reduction ----
    #pragma unroll
    for (int o = 16; o > 0; o >>= 1) {
        lsum += __shfl_xor_sync(0xFFFFFFFFu, lsum, o);
        lcnt += __shfl_xor_sync(0xFFFFFFFFu, lcnt, o);
    }
    if ((t & 31) == 0) { rsum[t >> 5] = lsum; rcnt[t >> 5] = lcnt; }
    __syncthreads();
    if (t == 0) {
        float S = 0.f; int C = 0;
        #pragma unroll
        for (int w = 0; w < NTHREADS / 32; w++) { S += rsum[w]; C += rcnt[w]; }
        g_psum[blockIdx.x] = S;
        g_pcnt[blockIdx.x] = C;
    }
}

// ---------------------------------------------------------------------------
// Kernel 3: finalize — deterministic reduction of 128 block partials.
// ---------------------------------------------------------------------------
__global__ __launch_bounds__(NBLOCKS) void finalize_kernel(float* __restrict__ out) {
    const int t = threadIdx.x;   // NBLOCKS = 128 threads
    float s = g_psum[t];
    int   c = g_pcnt[t];
    #pragma unroll
    for (int o = 16; o > 0; o >>= 1) {
        s += __shfl_xor_sync(0xFFFFFFFFu, s, o);
        c += __shfl_xor_sync(0xFFFFFFFFu, c, o);
    }
    __shared__ float ss[NBLOCKS / 32];
    __shared__ int   sc[NBLOCKS / 32];
    if ((t & 31) == 0) { ss[t >> 5] = s; sc[t >> 5] = c; }
    __syncthreads();
    if (t == 0) {
        float S = 0.f; int C = 0;
        #pragma unroll
        for (int w = 0; w < NBLOCKS / 32; w++) { S += ss[w]; C += sc[w]; }
        out[0] = S / (float)(C > 0 ? C : 1);
    }
}

extern "C" void kernel_launch(void* const* d_in, const int* in_sizes, int n_in,
                              void* d_out, int out_size) {
    (void)in_sizes; (void)n_in; (void)out_size;
    const float* emb  = (const float*)d_in[0];
    const int*   cats = (const int*)d_in[1];   // JAX default x64-disabled -> int32
    float* out = (float*)d_out;

    normalize_kernel<<<NB, ND>>>(emb);

    const size_t smem_bytes = (size_t)2 * ND * TI * sizeof(float);   // 128 KB
    cudaFuncSetAttribute(loss_kernel, cudaFuncAttributeMaxDynamicSharedMemorySize,
                         (int)smem_bytes);
    loss_kernel<<<NBLOCKS, NTHREADS, smem_bytes>>>(cats);

    finalize_kernel<<<1, NBLOCKS>>>(out);
}

// round 4
// speedup vs baseline: 9.7856x; 9.7856x over previous
#include <cuda_runtime.h>
#include <cuda_bf16.h>
#include <cstdint>
#include <math.h>

// ---------------- problem constants ----------------
#define NB 8192
#define ND 256
#define TI 128                   // anchors per CTA
#define TJP 128                  // j columns per pass
#define JSPLIT 2
#define JRANGE (NB / JSPLIT)     // 4096
#define NPASS (JRANGE / TJP)     // 32
#define NTHREADS 256
#define NCTAS ((NB / TI) * JSPLIT)  // 128

#define SCALE 2.0609929155556619f   // log2(e)/0.7 -> accum in log2 domain
#define C_MAX SCALE
#define LN2F  0.6931471805599453f

// SMEM: A tile + 2 B buffers, 528-byte row pitch (256 bf16 + 8 pad) for
// conflict-free ldmatrix (528/4 mod 32 = 4 -> 8 rows spread over banks).
#define PITCH 528
#define SM_A  0
#define SM_B0 (TI * PITCH)           // 67584
#define SM_BSZ (TJP * PITCH)         // 67584
#define SMEM_DYN (SM_B0 + 2 * SM_BSZ)  // 202752

// ---------------- device scratch ----------------
__device__ __nv_bfloat16 g_a[NB * ND];  // bf16(e * SCALE)  (A side)
__device__ __nv_bfloat16 g_b[NB * ND];  // bf16(e)          (B side)
__device__ float g_pp [JSPLIT * NB];    // per (j-half, anchor) max positive (log2 dom)
__device__ float g_pns[JSPLIT * NB];    // per (j-half, anchor) sum exp2 over negatives

// ---------------- PTX helpers (baseline sm_80+ features only) ----------------
__device__ __forceinline__ uint32_t smem_u32(const void* p) {
    uint32_t a;
    asm("{ .reg .u64 t; cvta.to.shared.u64 t, %1; cvt.u32.u64 %0, t; }" : "=r"(a) : "l"(p));
    return a;
}
__device__ __forceinline__ void cpa16(uint32_t dst, const void* src) {
    asm volatile("cp.async.cg.shared.global [%0], [%1], 16;" :: "r"(dst), "l"(src));
}
#define CP_COMMIT() asm volatile("cp.async.commit_group;" ::: "memory")
#define CP_WAIT1()  asm volatile("cp.async.wait_group 1;" ::: "memory")
#define CP_WAIT0()  asm volatile("cp.async.wait_group 0;" ::: "memory")

#define LDM_X4(r, addr)                                                        \
    asm volatile("ldmatrix.sync.aligned.m8n8.x4.shared.b16 {%0,%1,%2,%3}, [%4];" \
                 : "=r"((r)[0]), "=r"((r)[1]), "=r"((r)[2]), "=r"((r)[3])      \
                 : "r"(addr))
#define LDM_X4T(r, addr)                                                       \
    asm volatile("ldmatrix.sync.aligned.m8n8.x4.trans.shared.b16 {%0,%1,%2,%3}, [%4];" \
                 : "=r"((r)[0]), "=r"((r)[1]), "=r"((r)[2]), "=r"((r)[3])      \
                 : "r"(addr))

#define MMA_BF16(c, a, b0, b1)                                                 \
    asm volatile("mma.sync.aligned.m16n8k16.row.col.f32.bf16.bf16.f32 "        \
                 "{%0,%1,%2,%3}, {%4,%5,%6,%7}, {%8,%9}, {%0,%1,%2,%3};"       \
                 : "+f"((c)[0]), "+f"((c)[1]), "+f"((c)[2]), "+f"((c)[3])      \
                 : "r"((a)[0]), "r"((a)[1]), "r"((a)[2]), "r"((a)[3]),         \
                   "r"(b0), "r"(b1))

// ---------------- kernel 1: normalize + scaled/unscaled bf16 ----------------
__global__ __launch_bounds__(ND) void normalize_kernel(const float* __restrict__ emb) {
    const int row = blockIdx.x;
    const int t = threadIdx.x;
    float v = emb[row * ND + t];
    float s = v * v;
    #pragma unroll
    for (int o = 16; o > 0; o >>= 1) s += __shfl_xor_sync(0xFFFFFFFFu, s, o);
    __shared__ float ws[ND / 32];
    if ((t & 31) == 0) ws[t >> 5] = s;
    __syncthreads();
    float tot = 0.f;
    #pragma unroll
    for (int w = 0; w < ND / 32; w++) tot += ws[w];
    const float e = v * rsqrtf(tot);
    const int idx = row * ND + t;
    g_a[idx] = __float2bfloat16(e * SCALE);
    g_b[idx] = __float2bfloat16(e);
}

// ---------------- kernel 2: HMMA fused sims + contrastive stats -------------
__global__ __launch_bounds__(NTHREADS) void loss_kernel(const int* __restrict__ cats) {
    extern __shared__ __align__(16) char sp[];
    const uint32_t sb = smem_u32(sp);

    __shared__ int s_catI[TI];
    __shared__ int s_catJ[2][TJP];

    const int t    = threadIdx.x;
    const int wid  = t >> 5;
    const int lane = t & 31;
    const int g    = lane >> 2;
    const int tg   = lane & 3;
    const int wrow = wid >> 2;       // 0..1  (64 anchor rows each)
    const int wcol = wid & 3;        // 0..3  (32 j cols each)
    const int it   = blockIdx.x >> 1;
    const int jh   = blockIdx.x & 1;
    const int i0   = it * TI;
    const int j0   = jh * JRANGE;

    // ---- prologue: cp.async A tile + B pass 0, categories ----
    {
        const __nv_bfloat16* Ag = g_a + (size_t)i0 * ND;
        const __nv_bfloat16* Bg = g_b + (size_t)j0 * ND;
        #pragma unroll
        for (int m = 0; m < 16; m++) {
            const int idx = t + NTHREADS * m;   // 4096 chunks of 16B
            const int r = idx >> 5, ch = idx & 31;
            cpa16(sb + SM_A + r * PITCH + ch * 16, Ag + r * ND + ch * 8);
        }
        #pragma unroll
        for (int m = 0; m < 16; m++) {
            const int idx = t + NTHREADS * m;
            const int r = idx >> 5, ch = idx & 31;
            cpa16(sb + SM_B0 + r * PITCH + ch * 16, Bg + r * ND + ch * 8);
        }
        CP_COMMIT();
        if (t < TI)  s_catI[t]    = cats[i0 + t];
        if (t < TJP) s_catJ[0][t] = cats[j0 + t];
    }
    __syncthreads();   // s_catI visible

    // per-thread row/col bookkeeping (8 row slots, 8 col slots)
    int rowidx[8], iglob[8], ci[8], jcol[8];
    #pragma unroll
    for (int rs = 0; rs < 8; rs++) {
        rowidx[rs] = wrow * 64 + (rs >> 1) * 16 + (rs & 1) * 8 + g;
        iglob[rs]  = i0 + rowidx[rs];
        ci[rs]     = s_catI[rowidx[rs]];
    }
    #pragma unroll
    for (int cs = 0; cs < 8; cs++)
        jcol[cs] = wcol * 32 + (cs >> 1) * 8 + 2 * tg + (cs & 1);

    // ldmatrix per-lane address offsets
    const uint32_t a_lane = (uint32_t)(((lane & 7) + ((lane >> 3) & 1) * 8) * PITCH
                                       + (lane >> 4) * 16);
    const uint32_t b_lane = (uint32_t)(((lane & 7) + (lane >> 4) * 8) * PITCH
                                       + ((lane >> 3) & 1) * 16);
    const uint32_t aw = sb + SM_A + (uint32_t)(wrow * 64) * PITCH + a_lane;

    float pm[8], nsum[8];
    #pragma unroll
    for (int rs = 0; rs < 8; rs++) { pm[rs] = -1e30f; nsum[rs] = 0.f; }

    for (int ps = 0; ps < NPASS; ps++) {
        const int buf = ps & 1, nxt = (ps + 1) & 1;

        if (ps + 1 < NPASS) {
            const __nv_bfloat16* Bg = g_b + (size_t)(j0 + (ps + 1) * TJP) * ND;
            #pragma unroll
            for (int m = 0; m < 16; m++) {
                const int idx = t + NTHREADS * m;
                const int r = idx >> 5, ch = idx & 31;
                cpa16(sb + SM_B0 + nxt * SM_BSZ + r * PITCH + ch * 16, Bg + r * ND + ch * 8);
            }
            if (t < TJP) s_catJ[nxt][t] = cats[j0 + (ps + 1) * TJP + t];
            CP_COMMIT();
            CP_WAIT1();
        } else {
            CP_WAIT0();
        }
        __syncthreads();

        // ---- GEMM: warp tile 64x32, K=256 ----
        float c[4][4][4];
        #pragma unroll
        for (int mt = 0; mt < 4; mt++)
            #pragma unroll
            for (int nt = 0; nt < 4; nt++)
                #pragma unroll
                for (int q = 0; q < 4; q++) c[mt][nt][q] = 0.f;

        const uint32_t bw = sb + SM_B0 + (uint32_t)buf * SM_BSZ
                            + (uint32_t)(wcol * 32) * PITCH + b_lane;
        #pragma unroll
        for (int ks = 0; ks < 16; ks++) {
            uint32_t a[4][4], bt[2][4];
            #pragma unroll
            for (int mt = 0; mt < 4; mt++)
                LDM_X4(a[mt], aw + (uint32_t)(mt * 16) * PITCH + ks * 32);
            #pragma unroll
            for (int np = 0; np < 2; np++)
                LDM_X4T(bt[np], bw + (uint32_t)(np * 16) * PITCH + ks * 32);
            #pragma unroll
            for (int mt = 0; mt < 4; mt++)
                #pragma unroll
                for (int nt = 0; nt < 4; nt++)
                    MMA_BF16(c[mt][nt], a[mt], bt[nt >> 1][(nt & 1) * 2],
                             bt[nt >> 1][(nt & 1) * 2 + 1]);
        }

        // ---- epilogue: masked max-pos / sum-exp2-neg in log2 domain ----
        const int jb = j0 + ps * TJP;
        int cj[8];
        #pragma unroll
        for (int cs = 0; cs < 8; cs++) cj[cs] = s_catJ[buf][jcol[cs]];

        #pragma unroll
        for (int mt = 0; mt < 4; mt++) {
            #pragma unroll
            for (int h = 0; h < 2; h++) {
                const int rs = mt * 2 + h;
                #pragma unroll
                for (int nt = 0; nt < 4; nt++) {
                    #pragma unroll
                    for (int l = 0; l < 2; l++) {
                        const int q = h * 2 + l;
                        const int cs = nt * 2 + l;
                        const float v2 = c[mt][nt][q];
                        const bool same = (ci[rs] == cj[cs]);
                        float ev;
                        asm("ex2.approx.f32 %0, %1;" : "=f"(ev) : "f"(v2));
                        if (!same) nsum[rs] += ev;
                        const bool pos = same && (iglob[rs] != jb + jcol[cs]);
                        pm[rs] = fmaxf(pm[rs], pos ? v2 : -1e30f);
                    }
                }
            }
        }
        __syncthreads();   // all reads of buf done before next-iter prefetch overwrites
    }

    // ---- reduce: 4 lanes (tg) via shfl, 4 warp-cols via smem (alias A tile) ----
    float* redp = (float*)sp;            // [128][4]
    float* redn = (float*)(sp + 2048);   // [128][4]
    #pragma unroll
    for (int rs = 0; rs < 8; rs++) {
        float p = pm[rs], n = nsum[rs];
        p = fmaxf(p, __shfl_xor_sync(0xFFFFFFFFu, p, 1));
        p = fmaxf(p, __shfl_xor_sync(0xFFFFFFFFu, p, 2));
        n += __shfl_xor_sync(0xFFFFFFFFu, n, 1);
        n += __shfl_xor_sync(0xFFFFFFFFu, n, 2);
        if (tg == 0) {
            redp[rowidx[rs] * 4 + wcol] = p;
            redn[rowidx[rs] * 4 + wcol] = n;
        }
    }
    __syncthreads();
    if (t < TI) {
        float p = redp[t * 4 + 0], n = redn[t * 4 + 0];
        #pragma unroll
        for (int w = 1; w < 4; w++) {
            p = fmaxf(p, redp[t * 4 + w]);
            n += redn[t * 4 + w];
        }
        g_pp [jh * NB + i0 + t] = p;
        g_pns[jh * NB + i0 + t] = n;
    }
}

// ---------------- kernel 3: finalize ----------------
__global__ __launch_bounds__(1024) void finalize_kernel(float* __restrict__ out) {
    const int t = threadIdx.x;
    float lsum = 0.f;
    int lcnt = 0;
    const float inv2C = exp2f(-C_MAX);
    for (int i = t; i < NB; i += 1024) {
        const float p = fmaxf(g_pp[i], g_pp[NB + i]);
        const float s = g_pns[i] + g_pns[NB + i];
        if (p > -1e29f && s > 0.f) {
            // loss = ln2 * ( log2( 2^(p-C) + s*2^-C ) + C - p )
            const float l = LN2F * (log2f(exp2f(p - C_MAX) + s * inv2C) + C_MAX - p);
            lsum += l;
            lcnt += 1;
        }
    }
    #pragma unroll
    for (int o = 16; o > 0; o >>= 1) {
        lsum += __shfl_xor_sync(0xFFFFFFFFu, lsum, o);
        lcnt += __shfl_xor_sync(0xFFFFFFFFu, lcnt, o);
    }
    __shared__ float ss[32];
    __shared__ int sc[32];
    if ((t & 31) == 0) { ss[t >> 5] = lsum; sc[t >> 5] = lcnt; }
    __syncthreads();
    if (t == 0) {
        float S = 0.f; int C = 0;
        #pragma unroll
        for (int w = 0; w < 32; w++) { S += ss[w]; C += sc[w]; }
        out[0] = S / (float)(C > 0 ? C : 1);
    }
}

extern "C" void kernel_launch(void* const* d_in, const int* in_sizes, int n_in,
                              void* d_out, int out_size) {
    (void)in_sizes; (void)n_in; (void)out_size;
    const float* emb  = (const float*)d_in[0];
    const int*   cats = (const int*)d_in[1];   // JAX x64-disabled -> int32
    float* out = (float*)d_out;

    normalize_kernel<<<NB, ND>>>(emb);

    cudaFuncSetAttribute(loss_kernel, cudaFuncAttributeMaxDynamicSharedMemorySize, SMEM_DYN);
    loss_kernel<<<NCTAS, NTHREADS, SMEM_DYN>>>(cats);

    finalize_kernel<<<1, 1024>>>(out);
}

// round 6
// speedup vs baseline: 16.3346x; 1.6693x over previous
#include <cuda_runtime.h>
#include <cuda_bf16.h>
#include <cstdint>
#include <math.h>

// ---------------- problem constants ----------------
#define NB 8192
#define ND 256
#define TI 128
#define NSTRIP (NB / TI)                       // 64
#define NTILES ((NSTRIP * (NSTRIP + 1)) / 2)   // 2080 upper-triangle tiles
#define NCTAS 148
#define NTHREADS 256

#define SCALE 2.0609929155556619f   // log2(e)/0.7 -> accumulators in log2 domain
#define C_MAX SCALE
#define LN2F  0.6931471805599453f

// SMEM: A strip + 2 B buffers (PITCH=528 anti-conflict) + col-reduce scratch
#define PITCH 528
#define ASZ (TI * PITCH)            // 67584
#define SM_A  0
#define SM_B0 ASZ
#define BSZ   ASZ
#define SM_RED (SM_B0 + 2 * BSZ)    // 202752
#define SMEM_DYN (SM_RED + 2048)    // 204800

// ---------------- device scratch ----------------
__device__ __nv_bfloat16 g_a[NB * ND];   // bf16(e * SCALE)
__device__ __nv_bfloat16 g_b[NB * ND];   // bf16(e)
__device__ unsigned int  g_pk [NB];      // per-anchor pos-max, monotone-uint encoded
__device__ float         g_pns[NB];      // per-anchor sum exp2 over negatives

// ---------------- PTX helpers ----------------
__device__ __forceinline__ uint32_t smem_u32(const void* p) {
    uint32_t a;
    asm("{ .reg .u64 t; cvta.to.shared.u64 t, %1; cvt.u32.u64 %0, t; }" : "=r"(a) : "l"(p));
    return a;
}
__device__ __forceinline__ void cpa16(uint32_t dst, const void* src) {
    asm volatile("cp.async.cg.shared.global [%0], [%1], 16;" :: "r"(dst), "l"(src));
}
#define CP_COMMIT() asm volatile("cp.async.commit_group;" ::: "memory")
#define CP_WAIT1()  asm volatile("cp.async.wait_group 1;" ::: "memory")
#define CP_WAIT0()  asm volatile("cp.async.wait_group 0;" ::: "memory")

#define LDM_X4(r, addr)                                                          \
    asm volatile("ldmatrix.sync.aligned.m8n8.x4.shared.b16 {%0,%1,%2,%3}, [%4];" \
                 : "=r"((r)[0]), "=r"((r)[1]), "=r"((r)[2]), "=r"((r)[3])        \
                 : "r"(addr))
#define LDM_X4T(r, addr)                                                         \
    asm volatile("ldmatrix.sync.aligned.m8n8.x4.trans.shared.b16 {%0,%1,%2,%3}, [%4];" \
                 : "=r"((r)[0]), "=r"((r)[1]), "=r"((r)[2]), "=r"((r)[3])        \
                 : "r"(addr))
#define MMA_BF16(c, a, b0, b1)                                                   \
    asm volatile("mma.sync.aligned.m16n8k16.row.col.f32.bf16.bf16.f32 "          \
                 "{%0,%1,%2,%3}, {%4,%5,%6,%7}, {%8,%9}, {%0,%1,%2,%3};"         \
                 : "+f"((c)[0]), "+f"((c)[1]), "+f"((c)[2]), "+f"((c)[3])        \
                 : "r"((a)[0]), "r"((a)[1]), "r"((a)[2]), "r"((a)[3]),           \
                   "r"(b0), "r"(b1))

// monotone float->uint encoding (order-preserving; 0 = "none")
__device__ __forceinline__ unsigned int enc_f(float x) {
    unsigned int b = __float_as_uint(x);
    return (b & 0x80000000u) ? ~b : (b | 0x80000000u);
}
__device__ __forceinline__ float dec_f(unsigned int u) {
    unsigned int b = (u & 0x80000000u) ? (u & 0x7FFFFFFFu) : ~u;
    return __uint_as_float(b);
}

// ---------------- kernel 0: zero accumulators (graph replays!) --------------
__global__ __launch_bounds__(1024) void init_kernel() {
    const int i = blockIdx.x * 1024 + threadIdx.x;
    if (i < NB) { g_pk[i] = 0u; g_pns[i] = 0.f; }
}

// ---------------- kernel 1: normalize, warp-per-row -------------------------
__global__ __launch_bounds__(NTHREADS) void normalize_kernel(const float* __restrict__ emb) {
    const int wid  = threadIdx.x >> 5;
    const int lane = threadIdx.x & 31;
    const int row  = blockIdx.x * 8 + wid;
    const float4* src = (const float4*)(emb + (size_t)row * ND);
    const float4 v0 = src[lane * 2];
    const float4 v1 = src[lane * 2 + 1];
    float s = v0.x * v0.x + v0.y * v0.y + v0.z * v0.z + v0.w * v0.w
            + v1.x * v1.x + v1.y * v1.y + v1.z * v1.z + v1.w * v1.w;
    #pragma unroll
    for (int o = 16; o > 0; o >>= 1) s += __shfl_xor_sync(0xFFFFFFFFu, s, o);
    const float inv = rsqrtf(s);
    float e[8] = { v0.x * inv, v0.y * inv, v0.z * inv, v0.w * inv,
                   v1.x * inv, v1.y * inv, v1.z * inv, v1.w * inv };
    uint4 pa, pb;
    uint32_t* paw = (uint32_t*)&pa;
    uint32_t* pbw = (uint32_t*)&pb;
    #pragma unroll
    for (int q = 0; q < 4; q++) {
        __nv_bfloat162 ha = __floats2bfloat162_rn(e[2 * q] * SCALE, e[2 * q + 1] * SCALE);
        __nv_bfloat162 hb = __floats2bfloat162_rn(e[2 * q], e[2 * q + 1]);
        paw[q] = *(uint32_t*)&ha;
        pbw[q] = *(uint32_t*)&hb;
    }
    ((uint4*)(g_a + (size_t)row * ND))[lane] = pa;
    ((uint4*)(g_b + (size_t)row * ND))[lane] = pb;
}

// ---------------- kernel 2: triangular persistent-tile HMMA -----------------
__global__ __launch_bounds__(NTHREADS) void loss_kernel(const int* __restrict__ cats) {
    extern __shared__ __align__(16) char sp[];
    const uint32_t sb = smem_u32(sp);
    float* sredp = (float*)(sp + SM_RED);          // [2][128]
    float* sredn = (float*)(sp + SM_RED + 1024);   // [2][128]

    const int t    = threadIdx.x;
    const int wid  = t >> 5;
    const int lane = t & 31;
    const int g    = lane >> 2;
    const int tg   = lane & 3;
    const int wrow = wid >> 2;     // 0..1
    const int wcol = wid & 3;      // 0..3

    // tile chunk [k0, k1)
    const int k0 = (int)(((long long)NTILES * blockIdx.x) / NCTAS);
    const int k1 = (int)(((long long)NTILES * (blockIdx.x + 1)) / NCTAS);

    // decode k0 -> (it, jt)
    int it = 0, acc = 0;
    while (acc + (NSTRIP - it) <= k0) { acc += NSTRIP - it; it++; }
    int jt = it + (k0 - acc);

    // fragment coordinate bookkeeping
    int rowidx[8], jcol[8];
    #pragma unroll
    for (int rs = 0; rs < 8; rs++) {
        rowidx[rs] = wrow * 64 + (rs >> 1) * 16 + (rs & 1) * 8 + g;
    }
    #pragma unroll
    for (int cs = 0; cs < 8; cs++) {
        jcol[cs] = wcol * 32 + (cs >> 1) * 8 + 2 * tg + (cs & 1);
    }

    const uint32_t a_lane = (uint32_t)(((lane & 7) + ((lane >> 3) & 1) * 8) * PITCH
                                       + (lane >> 4) * 16);
    const uint32_t b_lane = (uint32_t)(((lane & 7) + (lane >> 4) * 8) * PITCH
                                       + ((lane >> 3) & 1) * 16);

    // prologue: load A(it) + B(jt) into buf0
    {
        const __nv_bfloat16* Ag = g_a + (size_t)it * TI * ND;
        const __nv_bfloat16* Bg = g_b + (size_t)jt * TI * ND;
        #pragma unroll
        for (int m = 0; m < 16; m++) {
            const int idx = t + NTHREADS * m;
            const int r = idx >> 5, ch = idx & 31;
            cpa16(sb + SM_A + r * PITCH + ch * 16, Ag + r * ND + ch * 8);
        }
        #pragma unroll
        for (int m = 0; m < 16; m++) {
            const int idx = t + NTHREADS * m;
            const int r = idx >> 5, ch = idx & 31;
            cpa16(sb + SM_B0 + r * PITCH + ch * 16, Bg + r * ND + ch * 8);
        }
        CP_COMMIT();
    }

    int ci[8];
    #pragma unroll
    for (int rs = 0; rs < 8; rs++) {
        ci[rs] = cats[it * TI + rowidx[rs]];
    }

    float pmr[8], nsr[8];
    #pragma unroll
    for (int rs = 0; rs < 8; rs++) { pmr[rs] = -1e30f; nsr[rs] = 0.f; }

    int buf = 0;
    for (int k = k0; k < k1; k++) {
        const bool haveNext = (k + 1 < k1);
        int nit = it, njt = jt + 1;
        if (njt == NSTRIP) { nit = it + 1; njt = nit; }

        // prefetch next B tile (buf^1: last read by GEMM(k-1), synced at end of prev iter)
        if (haveNext) {
            const __nv_bfloat16* Bg = g_b + (size_t)njt * TI * ND;
            const uint32_t dst = sb + SM_B0 + (uint32_t)(buf ^ 1) * BSZ;
            #pragma unroll
            for (int m = 0; m < 16; m++) {
                const int idx = t + NTHREADS * m;
                const int r = idx >> 5, ch = idx & 31;
                cpa16(dst + r * PITCH + ch * 16, Bg + r * ND + ch * 8);
            }
            CP_COMMIT();
            CP_WAIT1();     // A(current strip) + B(k) complete
        } else {
            CP_WAIT0();
        }
        __syncthreads();

        // ---- GEMM 128x128x256 ----
        float c[4][4][4];
        #pragma unroll
        for (int mt = 0; mt < 4; mt++) {
            #pragma unroll
            for (int nt = 0; nt < 4; nt++) {
                #pragma unroll
                for (int q = 0; q < 4; q++) { c[mt][nt][q] = 0.f; }
            }
        }

        const uint32_t aw = sb + SM_A + (uint32_t)(wrow * 64) * PITCH + a_lane;
        const uint32_t bw = sb + SM_B0 + (uint32_t)buf * BSZ
                            + (uint32_t)(wcol * 32) * PITCH + b_lane;
        #pragma unroll
        for (int ks = 0; ks < 16; ks++) {
            uint32_t a[4][4], bt[2][4];
            #pragma unroll
            for (int mt = 0; mt < 4; mt++) {
                LDM_X4(a[mt], aw + (uint32_t)(mt * 16) * PITCH + ks * 32);
            }
            #pragma unroll
            for (int np = 0; np < 2; np++) {
                LDM_X4T(bt[np], bw + (uint32_t)(np * 16) * PITCH + ks * 32);
            }
            #pragma unroll
            for (int mt = 0; mt < 4; mt++) {
                #pragma unroll
                for (int nt = 0; nt < 4; nt++) {
                    MMA_BF16(c[mt][nt], a[mt], bt[nt >> 1][(nt & 1) * 2],
                             bt[nt >> 1][(nt & 1) * 2 + 1]);
                }
            }
        }
        __syncthreads();   // all reads of A and B[buf] complete

        // strip changes next tile: A reload can start now, overlaps epilogue
        if (haveNext && nit != it) {
            const __nv_bfloat16* Ag = g_a + (size_t)nit * TI * ND;
            #pragma unroll
            for (int m = 0; m < 16; m++) {
                const int idx = t + NTHREADS * m;
                const int r = idx >> 5, ch = idx & 31;
                cpa16(sb + SM_A + r * PITCH + ch * 16, Ag + r * ND + ch * 8);
            }
            CP_COMMIT();
        }

        // ---- epilogue ----
        const int j0 = jt * TI;
        int cj[8];
        #pragma unroll
        for (int cs = 0; cs < 8; cs++) {
            cj[cs] = cats[j0 + jcol[cs]];
        }

        const bool isdiag = (it == jt);

        if (isdiag) {
            #pragma unroll
            for (int mt = 0; mt < 4; mt++) {
                #pragma unroll
                for (int h = 0; h < 2; h++) {
                    const int rs = mt * 2 + h;
                    #pragma unroll
                    for (int nt = 0; nt < 4; nt++) {
                        #pragma unroll
                        for (int l = 0; l < 2; l++) {
                            const int cs = nt * 2 + l;
                            const float v2 = c[mt][nt][h * 2 + l];
                            float ev;
                            asm("ex2.approx.f32 %0, %1;" : "=f"(ev) : "f"(v2));
                            const bool same = (ci[rs] == cj[cs]);
                            if (!same) { nsr[rs] += ev; }
                            else if (rowidx[rs] != jcol[cs]) { pmr[rs] = fmaxf(pmr[rs], v2); }
                        }
                    }
                }
            }
        } else {
            float pmc[8], nsc[8];
            #pragma unroll
            for (int cs = 0; cs < 8; cs++) { pmc[cs] = -1e30f; nsc[cs] = 0.f; }

            #pragma unroll
            for (int mt = 0; mt < 4; mt++) {
                #pragma unroll
                for (int h = 0; h < 2; h++) {
                    const int rs = mt * 2 + h;
                    #pragma unroll
                    for (int nt = 0; nt < 4; nt++) {
                        #pragma unroll
                        for (int l = 0; l < 2; l++) {
                            const int cs = nt * 2 + l;
                            const float v2 = c[mt][nt][h * 2 + l];
                            float ev;
                            asm("ex2.approx.f32 %0, %1;" : "=f"(ev) : "f"(v2));
                            const bool same = (ci[rs] == cj[cs]);
                            if (same) {
                                pmr[rs] = fmaxf(pmr[rs], v2);
                                pmc[cs] = fmaxf(pmc[cs], v2);
                            } else {
                                nsr[rs] += ev;
                                nsc[cs] += ev;
                            }
                        }
                    }
                }
            }

            // column reduce over g-lanes, then cross-wrow combine + atomics
            #pragma unroll
            for (int cs = 0; cs < 8; cs++) {
                float p = pmc[cs], n = nsc[cs];
                #pragma unroll
                for (int o = 4; o < 32; o <<= 1) {
                    p = fmaxf(p, __shfl_xor_sync(0xFFFFFFFFu, p, o));
                    n += __shfl_xor_sync(0xFFFFFFFFu, n, o);
                }
                pmc[cs] = p; nsc[cs] = n;
            }
            if (lane < 4) {
                #pragma unroll
                for (int cs = 0; cs < 8; cs++) {
                    const int col = wcol * 32 + (cs >> 1) * 8 + 2 * lane + (cs & 1);
                    sredp[wrow * 128 + col] = pmc[cs];
                    sredn[wrow * 128 + col] = nsc[cs];
                }
            }
            __syncthreads();
            if (t < TI) {
                const float p = fmaxf(sredp[t], sredp[128 + t]);
                const float n = sredn[t] + sredn[128 + t];
                if (p > -1e29f) { atomicMax(&g_pk[j0 + t], enc_f(p)); }
                if (n != 0.f)   { atomicAdd(&g_pns[j0 + t], n); }
            }
        }

        // strip boundary: flush row stats, refresh ci
        if (haveNext && nit != it) {
            #pragma unroll
            for (int rs = 0; rs < 8; rs++) {
                const int ig = it * TI + rowidx[rs];
                if (pmr[rs] > -1e29f) { atomicMax(&g_pk[ig], enc_f(pmr[rs])); }
                if (nsr[rs] != 0.f)   { atomicAdd(&g_pns[ig], nsr[rs]); }
                pmr[rs] = -1e30f; nsr[rs] = 0.f;
                ci[rs] = cats[nit * TI + rowidx[rs]];
            }
        }
        __syncthreads();   // epilogue reads (cj/sred/B) done before next prefetch writes
        it = nit; jt = njt; buf ^= 1;
    }

    // final row flush
    #pragma unroll
    for (int rs = 0; rs < 8; rs++) {
        const int ig = it * TI + rowidx[rs];
        if (pmr[rs] > -1e29f) { atomicMax(&g_pk[ig], enc_f(pmr[rs])); }
        if (nsr[rs] != 0.f)   { atomicAdd(&g_pns[ig], nsr[rs]); }
    }
}

// ---------------- kernel 3: finalize ----------------
__global__ __launch_bounds__(1024) void finalize_kernel(float* __restrict__ out) {
    const int t = threadIdx.x;
    float lsum = 0.f;
    int lcnt = 0;
    const float inv2C = exp2f(-C_MAX);
    for (int i = t; i < NB; i += 1024) {
        const unsigned int key = g_pk[i];
        const float s = g_pns[i];
        if (key != 0u && s > 0.f) {
            const float p = dec_f(key);
            if (p > -1e29f) {
                const float l = LN2F * (log2f(exp2f(p - C_MAX) + s * inv2C) + C_MAX - p);
                lsum += l;
                lcnt += 1;
            }
        }
    }
    #pragma unroll
    for (int o = 16; o > 0; o >>= 1) {
        lsum += __shfl_xor_sync(0xFFFFFFFFu, lsum, o);
        lcnt += __shfl_xor_sync(0xFFFFFFFFu, lcnt, o);
    }
    __shared__ float ss[32];
    __shared__ int sc[32];
    if ((t & 31) == 0) { ss[t >> 5] = lsum; sc[t >> 5] = lcnt; }
    __syncthreads();
    if (t == 0) {
        float S = 0.f; int C = 0;
        #pragma unroll
        for (int w = 0; w < 32; w++) { S += ss[w]; C += sc[w]; }
        out[0] = S / (float)(C > 0 ? C : 1);
    }
}

extern "C" void kernel_launch(void* const* d_in, const int* in_sizes, int n_in,
                              void* d_out, int out_size) {
    (void)in_sizes; (void)n_in; (void)out_size;
    const float* emb  = (const float*)d_in[0];
    const int*   cats = (const int*)d_in[1];   // JAX x64-disabled -> int32
    float* out = (float*)d_out;

    init_kernel<<<(NB + 1023) / 1024, 1024>>>();
    normalize_kernel<<<NB / 8, NTHREADS>>>(emb);

    cudaFuncSetAttribute(loss_kernel, cudaFuncAttributeMaxDynamicSharedMemorySize, SMEM_DYN);
    loss_kernel<<<NCTAS, NTHREADS, SMEM_DYN>>>(cats);

    finalize_kernel<<<1, 1024>>>(out);
}